// round 7
// baseline (speedup 1.0000x reference)
#include <cuda_runtime.h>
#include <cuda_fp16.h>

#define NB     320
#define NHW    26
#define AREA   676
#define KPOS   3380
#define NBOX   50
#define NENT   (NB*NBOX)
#define CSZ    20
#define NMETA  20
#define DWROWS 64
#define DWCOLS 1024
#define QPB    845            // quads per image (KPOS/4)
#define NQUAD  (NB*QPB)       // 270400

#define N_ENEW 20
#define N_MAIN 1057           // ceil(NQUAD/256)
#define N_CORR 63             // ceil(NENT/256)
#define N_SAME 64
#define N_DIFF 20
#define B_MAIN0 N_ENEW
#define B_CORR0 (B_MAIN0 + N_MAIN)
#define B_SAME0 (B_CORR0 + N_CORR)
#define B_DIFF0 (B_SAME0 + N_SAME)
#define NBLOCKS (B_DIFF0 + N_DIFF)   // 1224

__constant__ float c_aw[5] = {1.3221f, 3.19275f, 5.05587f, 9.47112f, 11.2364f};
__constant__ float c_ah[5] = {1.73145f, 4.00944f, 8.09892f, 4.84053f, 10.0071f};

__device__ double g_acc;
__device__ int    g_done;
__device__ int    g_flag;
__device__ float  g_enews[NMETA*DWCOLS];
__device__ int    g_cnt[NMETA];

__device__ __forceinline__ float sigmoidf(float v){ return 1.f/(1.f+__expf(-v)); }
__device__ __forceinline__ unsigned duph(float v){
    return (unsigned)__half_as_ushort(__float2half_rn(v)) * 0x10001u;
}
union H2U { unsigned u; __half2 h; };
__device__ __forceinline__ __half2 u2h2(unsigned v){ H2U c; c.u = v; return c.h; }

struct BoxH { unsigned x1, x2, y1, y2, ns; };

// Bit-deterministic fp16 box build — used by BOTH main and corr so the
// silence test cancels exactly in the correction.
__device__ __forceinline__ BoxH box_from_tgt(const float* __restrict__ tgt, int e){
    const float* g = tgt + e*5;
    float g1 = g[1];
    BoxH r;
    if(g1 == 0.0f){
        unsigned far = duph(30000.f);
        r.x1 = r.x2 = r.y1 = r.y2 = far;   // degenerate: never silences
        r.ns = duph(-1.f);
        return r;
    }
    float gx = g1*26.f, gy = g[2]*26.f, gw = g[3]*26.f, gh = g[4]*26.f;
    r.x1 = duph(gx-0.5f*gw); r.x2 = duph(gx+0.5f*gw);
    r.y1 = duph(gy-0.5f*gh); r.y2 = duph(gy+0.5f*gh);
    r.ns = duph(-0.375f*gw*gh);
    return r;
}

__device__ __forceinline__ int cell_of_entry(const float* __restrict__ tgt, int e){
    const float* g = tgt + e*5;
    float g1 = g[1];
    if(g1 == 0.0f) return -1;
    float gx = g1*26.f, gy = g[2]*26.f, gw = g[3]*26.f, gh = g[4]*26.f;
    int bn = 0; float best = -1.f;
    #pragma unroll
    for(int a=0; a<5; a++){
        float inter = fminf(gw, c_aw[a]) * fminf(gh, c_ah[a]);
        float iou = inter / (gw*gh + c_aw[a]*c_ah[a] - inter);
        if(iou > best){ best = iou; bn = a; }
    }
    int gi = (int)gx; gi = min(max(gi,0), NHW-1);
    int gj = (int)gy; gj = min(max(gj,0), NHW-1);
    int b = e / NBOX;
    return b*KPOS + bn*AREA + gj*NHW + gi;
}

__global__ void __launch_bounds__(256) kALL(const float* __restrict__ out,
                                            const float* __restrict__ tgt,
                                            const float* __restrict__ dw,
                                            const int*   __restrict__ ids,
                                            float* __restrict__ res){
    int blk = blockIdx.x, tid = threadIdx.x;
    float local = 0.f;

    if(blk >= B_MAIN0 && blk < B_CORR0){
        // ---- default per-cell loss over global quad index, fp16x2 silence ----
        int mb = blk - B_MAIN0;
        int q  = mb*256 + tid;
        __shared__ uint4    sb[2][NBOX];
        __shared__ unsigned sns[2][NBOX];
        int b_first = (mb*256) / QPB;
        if(tid < NBOX){
            BoxH bx = box_from_tgt(tgt, b_first*NBOX + tid);
            sb[0][tid]  = make_uint4(bx.x1, bx.x2, bx.y1, bx.y2);
            sns[0][tid] = bx.ns;
        } else if(tid >= 64 && tid < 64 + NBOX){
            int b1 = min(b_first + 1, NB - 1);
            BoxH bx = box_from_tgt(tgt, b1*NBOX + (tid - 64));
            sb[1][tid-64]  = make_uint4(bx.x1, bx.x2, bx.y1, bx.y2);
            sns[1][tid-64] = bx.ns;
        }
        __syncthreads();

        if(q < NQUAD){
            int b  = q / QPB;
            int qa = q - b*QPB;
            int a  = qa / 169;
            int r0 = (qa - a*169) * 4;
            int sel = b - b_first;
            const float* p = out + ((b*5+a)*6)*AREA + r0;
            float4 xr = *(const float4*)(p);
            float4 yr = *(const float4*)(p +   AREA);
            float4 wr = *(const float4*)(p + 2*AREA);
            float4 hr = *(const float4*)(p + 3*AREA);
            float4 cr = *(const float4*)(p + 4*AREA);

            float pas[4], cvh[4];
            __half2 hx1[2], hx2[2], hy1[2], hy2[2];
            float base = 0.f;
            {
                float xa[4] = {xr.x, xr.y, xr.z, xr.w};
                float ya[4] = {yr.x, yr.y, yr.z, yr.w};
                float wa[4] = {wr.x, wr.y, wr.z, wr.w};
                float ha[4] = {hr.x, hr.y, hr.z, hr.w};
                float ca[4] = {cr.x, cr.y, cr.z, cr.w};
                float px1[4], px2[4], py1[4], py2[4];
                #pragma unroll
                for(int u=0; u<4; u++){
                    float xv = sigmoidf(xa[u]);
                    float yv = sigmoidf(ya[u]);
                    float wv = wa[u], hv = ha[u];
                    float cv = sigmoidf(ca[u]);
                    int r = r0 + u;
                    int j = r / NHW, i = r - j*NHW;
                    float pw = __expf(wv)*c_aw[a], ph = __expf(hv)*c_ah[a];
                    float px = xv + (float)i, py = yv + (float)j;
                    px1[u] = px - 0.5f*pw; px2[u] = px + 0.5f*pw;
                    py1[u] = py - 0.5f*ph; py2[u] = py + 0.5f*ph;
                    pas[u] = 0.375f*pw*ph;
                    float dx = xv-0.5f, dy = yv-0.5f;
                    base += 0.5f*(dx*dx + dy*dy + wv*wv + hv*hv);
                    cvh[u] = 0.5f*cv*cv;
                }
                hx1[0] = __floats2half2_rn(px1[0], px1[1]); hx1[1] = __floats2half2_rn(px1[2], px1[3]);
                hx2[0] = __floats2half2_rn(px2[0], px2[1]); hx2[1] = __floats2half2_rn(px2[2], px2[3]);
                hy1[0] = __floats2half2_rn(py1[0], py1[1]); hy1[1] = __floats2half2_rn(py1[2], py1[3]);
                hy2[0] = __floats2half2_rn(py2[0], py2[1]); hy2[1] = __floats2half2_rn(py2[2], py2[3]);
            }
            const uint4*    bp = sb[sel];
            const unsigned* np = sns[sel];
            __half2 zero2 = __float2half2_rn(0.f);
            __half2 acc0 = u2h2(0xFC00FC00u), acc1 = u2h2(0xFC00FC00u);
            #pragma unroll 10
            for(int t=0; t<NBOX; t++){
                uint4 B = bp[t];
                __half2 ns  = u2h2(np[t]);
                __half2 bx1 = u2h2(B.x), bx2 = u2h2(B.y), by1 = u2h2(B.z), by2 = u2h2(B.w);
                __half2 cw0 = __hsub2(__hmin2(hx2[0], bx2), __hmax2(hx1[0], bx1));
                cw0 = __hmax2(cw0, zero2);
                __half2 ch0 = __hsub2(__hmin2(hy2[0], by2), __hmax2(hy1[0], by1));
                acc0 = __hmax2(acc0, __hfma2(cw0, ch0, ns));
                __half2 cw1 = __hsub2(__hmin2(hx2[1], bx2), __hmax2(hx1[1], bx1));
                cw1 = __hmax2(cw1, zero2);
                __half2 ch1 = __hsub2(__hmin2(hy2[1], by2), __hmax2(hy1[1], by1));
                acc1 = __hmax2(acc1, __hfma2(cw1, ch1, ns));
            }
            float a0 = __low2float(acc0), a1 = __high2float(acc0);
            float a2 = __low2float(acc1), a3 = __high2float(acc1);
            base += (a0 > pas[0]) ? 0.f : cvh[0];
            base += (a1 > pas[1]) ? 0.f : cvh[1];
            base += (a2 > pas[2]) ? 0.f : cvh[2];
            base += (a3 > pas[3]) ? 0.f : cvh[3];
            local = base;
        }
    } else if(blk >= B_CORR0 && blk < B_SAME0){
        // ---- correction for matched (winner) entries, self-sufficient ----
        __shared__ int s_cell[256 + NBOX];
        int e0 = (blk - B_CORR0)*256;
        {
            int e1 = e0 + tid;
            s_cell[tid] = (e1 < NENT) ? cell_of_entry(tgt, e1) : -2;
            if(tid < NBOX){
                int e2 = e0 + 256 + tid;
                s_cell[256 + tid] = (e2 < NENT) ? cell_of_entry(tgt, e2) : -2;
            }
        }
        __syncthreads();
        int e = e0 + tid;
        if(e < NENT){
            int cell = s_cell[tid];
            if(cell >= 0){
                int b = e / NBOX, t0 = e - b*NBOX;
                bool winner = true;
                #pragma unroll 7
                for(int t2 = t0+1; t2 < NBOX; t2++)
                    winner &= (s_cell[tid + (t2 - t0)] != cell);
                if(winner){
                    const float* g = tgt + e*5;
                    float gx = g[1]*26.f, gy = g[2]*26.f, gw = g[3]*26.f, gh = g[4]*26.f;
                    int bn = 0; float best = -1.f;
                    #pragma unroll
                    for(int aa=0; aa<5; aa++){
                        float inter = fminf(gw, c_aw[aa]) * fminf(gh, c_ah[aa]);
                        float iou = inter / (gw*gh + c_aw[aa]*c_ah[aa] - inter);
                        if(iou > best){ best = iou; bn = aa; }
                    }
                    int gi = (int)gx; gi = min(max(gi,0), NHW-1);
                    int gj = (int)gy; gj = min(max(gj,0), NHW-1);
                    float tx = gx - (float)gi, ty = gy - (float)gj;
                    float twv = logf(gw / c_aw[bn]), thv = logf(gh / c_ah[bn]);

                    int k = cell - b*KPOS;
                    int a = k / AREA, r = k - a*AREA;
                    const float* p = out + ((b*5+a)*6)*AREA + r;
                    float xv = sigmoidf(p[0]);
                    float yv = sigmoidf(p[AREA]);
                    float wv = p[2*AREA];
                    float hv = p[3*AREA];
                    float cvv = sigmoidf(p[4*AREA]);
                    int j = r / NHW, i = r - j*NHW;
                    float pw = __expf(wv)*c_aw[a], ph = __expf(hv)*c_ah[a];
                    float px = xv + (float)i, py = yv + (float)j;
                    // tconf iou (fp32, exact)
                    float cwg = fminf(gx+0.5f*gw, px+0.5f*pw) - fmaxf(gx-0.5f*gw, px-0.5f*pw);
                    float chg = fminf(gy+0.5f*gh, py+0.5f*ph) - fmaxf(gy-0.5f*gh, py-0.5f*ph);
                    float interg = (cwg>0.f && chg>0.f) ? cwg*chg : 0.f;
                    float tconf = interg / (gw*gh + pw*ph - interg);
                    // silent: IDENTICAL fp16 path as main (boxes rebuilt bit-identically)
                    float px1 = px-0.5f*pw, px2 = px+0.5f*pw;
                    float py1 = py-0.5f*ph, py2 = py+0.5f*ph;
                    float pas = 0.375f*pw*ph;
                    __half2 hx1 = __float2half2_rn(px1), hx2 = __float2half2_rn(px2);
                    __half2 hy1 = __float2half2_rn(py1), hy2 = __float2half2_rn(py2);
                    __half2 zero2 = __float2half2_rn(0.f);
                    __half2 acch = u2h2(0xFC00FC00u);
                    for(int t=0; t<NBOX; t++){
                        BoxH bx = box_from_tgt(tgt, b*NBOX + t);
                        __half2 cw = __hsub2(__hmin2(hx2, u2h2(bx.x2)), __hmax2(hx1, u2h2(bx.x1)));
                        cw = __hmax2(cw, zero2);
                        __half2 ch = __hsub2(__hmin2(hy2, u2h2(bx.y2)), __hmax2(hy1, u2h2(bx.y1)));
                        acch = __hmax2(acch, __hfma2(cw, ch, u2h2(bx.ns)));
                    }
                    float acc = __low2float(acch);
                    float cmd = (acc > pas) ? 0.f : 1.f;
                    float dx0 = xv-0.5f, dy0 = yv-0.5f;
                    float ldft = 0.5f*(dx0*dx0 + dy0*dy0 + wv*wv + hv*hv + cmd*cvv*cvv);
                    float dx = xv-tx, dy = yv-ty, dwv = wv-twv,
                          dh = hv-thv, dc = cvv-tconf;
                    float lmat = 0.5f*(dx*dx + dy*dy + dwv*dwv + dh*dh + 5.f*dc*dc);
                    // class loss (winner cells only)
                    int bsi = b / CSZ, cc = b - bsi*CSZ;
                    float v[CSZ]; float m = -3.4e38f;
                    #pragma unroll
                    for(int c2=0; c2<CSZ; c2++){
                        v[c2] = out[((bsi*CSZ+c2)*30 + a*6 + 5)*AREA + r];
                        m = fmaxf(m, v[c2]);
                    }
                    float s = 0.f;
                    #pragma unroll
                    for(int c2=0; c2<CSZ; c2++) s += __expf(v[c2]-m);
                    float lse = m + __logf(s);
                    local = lmat - ldft + (lse - v[cc]);
                }
            }
        }
    } else if(blk < N_ENEW){
        // ---- per-class mean embeddings (grid front; publishes flag) ----
        int c = blk;
        __shared__ int sids[DWROWS];
        if(tid < DWROWS) sids[tid] = ids[tid];
        __syncthreads();
        int n = 0;
        #pragma unroll
        for(int r=0; r<DWROWS; r++) n += (sids[r] == c);
        if(tid == 0) g_cnt[c] = n;
        float inv = 1.f / (float)max(n, 1);
        for(int col = tid; col < DWCOLS; col += 256){
            float s = 0.f;
            #pragma unroll
            for(int r=0; r<DWROWS; r++){
                if(sids[r] == c) s += dw[r*DWCOLS + col];
            }
            g_enews[c*DWCOLS + col] = s * inv;
        }
        __syncthreads();
        if(tid == 0){
            __threadfence();
            atomicAdd(&g_flag, 1);
        }
    } else if(blk >= B_SAME0 && blk < B_DIFF0){
        // ---- "same" loss (waits for enews) ----
        if(tid == 0){ while(atomicAdd(&g_flag, 0) < N_ENEW) {} }
        __syncthreads();
        __threadfence();
        int idx4 = (blk - B_SAME0)*256 + tid;
        int base = idx4*4;
        int r = base >> 10, c = base & 1023;
        float4 d  = *(const float4*)(dw + base);
        const float* en = g_enews + ids[r]*DWCOLS + c;
        float4 ev = *(const float4*)en;
        float a0 = d.x-ev.x, a1 = d.y-ev.y, a2 = d.z-ev.z, a3 = d.w-ev.w;
        local = a0*a0 + a1*a1 + a2*a2 + a3*a3;
    } else {
        // ---- "different" loss (waits for enews) ----
        if(tid == 0){ while(atomicAdd(&g_flag, 0) < N_ENEW) {} }
        __syncthreads();
        __threadfence();
        int i = blk - B_DIFF0;
        float part[NMETA];
        #pragma unroll
        for(int j=0; j<NMETA; j++) part[j] = 0.f;
        for(int col=tid; col<DWCOLS; col+=256){
            float ei = g_enews[i*DWCOLS + col];
            #pragma unroll
            for(int j=0; j<NMETA; j++){
                float df = ei - g_enews[j*DWCOLS + col];
                part[j] += df*df;
            }
        }
        __shared__ float dmat[NMETA];
        if(tid < NMETA) dmat[tid] = 0.f;
        __syncthreads();
        int lane = tid & 31;
        #pragma unroll
        for(int j=0; j<NMETA; j++){
            float v = part[j];
            #pragma unroll
            for(int o=16; o>0; o>>=1) v += __shfl_xor_sync(0xffffffffu, v, o);
            if(lane == 0) atomicAdd(&dmat[j], v);
        }
        __syncthreads();
        if(tid == 0){
            bool pi = g_cnt[i] > 0;
            float dmin = 3.4e38f; bool any = false;
            for(int j=0; j<NMETA; j++){
                bool vp = pi && (g_cnt[j] > 0) && (j != i);
                if(vp){ any = true; dmin = fminf(dmin, dmat[j]); }
            }
            if(any) local = -dmin;
        }
    }

    // ---- block reduce (shuffle + smem atomic) + global accumulate + finalize ----
    #pragma unroll
    for(int o=16; o>0; o>>=1) local += __shfl_xor_sync(0xffffffffu, local, o);
    __shared__ float bsum;
    if(tid == 0) bsum = 0.f;
    __syncthreads();
    if((tid & 31) == 0 && local != 0.f) atomicAdd(&bsum, local);
    __syncthreads();
    if(tid == 0){
        atomicAdd(&g_acc, (double)bsum);
        __threadfence();
        int t = atomicAdd(&g_done, 1);
        if(t == NBLOCKS - 1){
            res[0] = (float)g_acc;
            g_acc  = 0.0;      // reset for next graph replay
            g_done = 0;
            g_flag = 0;
        }
    }
}

extern "C" void kernel_launch(void* const* d_in, const int* in_sizes, int n_in,
                              void* d_out, int out_size){
    const float* outp = (const float*)d_in[0];   // (320,30,26,26)
    const float* tgt  = (const float*)d_in[1];   // (16,20,250) == (320,50,5)
    const float* dwp  = (const float*)d_in[2];   // (1,64,1024)
    const int*   ids  = (const int*)d_in[3];     // (64,)
    float* res = (float*)d_out;

    kALL<<<NBLOCKS, 256>>>(outp, tgt, dwp, ids, res);
}

// round 8
// speedup vs baseline: 1.3101x; 1.3101x over previous
#include <cuda_runtime.h>
#include <cuda_fp16.h>

#define NB     320
#define NHW    26
#define AREA   676
#define KPOS   3380
#define NBOX   50
#define NENT   (NB*NBOX)
#define CSZ    20
#define NMETA  20
#define DWROWS 64
#define DWCOLS 1024
#define QPB    845            // quads per image
#define NQUAD  (NB*QPB)       // 270400

#define N_ENT   63
#define N_ENEW  20
#define N_MAIN  1057          // ceil(NQUAD/256)
#define N_CORR  63
#define N_SAME  64
#define N_DIFF  20
#define B_ENEW0 N_ENT                       // 63
#define B_MAIN0 (B_ENEW0 + N_ENEW)          // 83
#define B_CORR0 (B_MAIN0 + N_MAIN)          // 1140
#define B_SAME0 (B_CORR0 + N_CORR)          // 1203
#define B_DIFF0 (B_SAME0 + N_SAME)          // 1267
#define NBLOCKS (B_DIFF0 + N_DIFF)          // 1287

__constant__ float c_aw[5] = {1.3221f, 3.19275f, 5.05587f, 9.47112f, 11.2364f};
__constant__ float c_ah[5] = {1.73145f, 4.00944f, 8.09892f, 4.84053f, 10.0071f};

__device__ double g_acc;
__device__ int    g_done;
__device__ int    g_flag_ent;
__device__ int    g_flag_enew;
__device__ int    e_cell[NENT];
__device__ uint4  g_bh[NENT];       // duplicated half2: x1,x2,y1,y2
__device__ unsigned g_nsh[NENT];    // duplicated half2 of -(0.375*gw*gh)
__device__ float  g_enews[NMETA*DWCOLS];
__device__ int    g_cnt[NMETA];

__device__ __forceinline__ float sigmoidf(float v){ return 1.f/(1.f+__expf(-v)); }
__device__ __forceinline__ unsigned duph(float v){
    return (unsigned)__half_as_ushort(__float2half_rn(v)) * 0x10001u;
}
union H2U { unsigned u; __half2 h; };
__device__ __forceinline__ __half2 u2h2(unsigned v){ H2U c; c.u = v; return c.h; }

__global__ void __launch_bounds__(256, 5) kALL(const float* __restrict__ out,
                                               const float* __restrict__ tgt,
                                               const float* __restrict__ dw,
                                               const int*   __restrict__ ids,
                                               float* __restrict__ res){
    int blk = blockIdx.x, tid = threadIdx.x;
    float local = 0.f;

    if(blk >= B_MAIN0 && blk < B_CORR0){
        // ---- default per-cell loss over global quad index, fp16x2 silence ----
        int mb = blk - B_MAIN0;
        int q  = mb*256 + tid;
        __shared__ uint4    sb[2][NBOX];
        __shared__ unsigned sns[2][NBOX];
        int b_first = (mb*256) / QPB;
        {   // build fp16 box tables for the <=2 images this block spans
            int w = -1, bb2 = 0;
            if(tid < NBOX){ w = 0; bb2 = b_first; }
            else if(tid >= 64 && tid < 64 + NBOX){ w = 1; bb2 = min(b_first + 1, NB - 1); }
            if(w >= 0){
                int t = (w == 0) ? tid : tid - 64;
                const float* g = tgt + (bb2*NBOX + t)*5;
                float g1 = g[1];
                if(g1 == 0.0f){
                    unsigned far = duph(30000.f);
                    sb[w][t]  = make_uint4(far, far, far, far);
                    sns[w][t] = duph(-1.f);
                } else {
                    float gx = g1*26.f, gy = g[2]*26.f, gw = g[3]*26.f, gh = g[4]*26.f;
                    sb[w][t]  = make_uint4(duph(gx-0.5f*gw), duph(gx+0.5f*gw),
                                           duph(gy-0.5f*gh), duph(gy+0.5f*gh));
                    sns[w][t] = duph(-0.375f*gw*gh);
                }
            }
        }
        __syncthreads();

        if(q < NQUAD){
            int b  = q / QPB;
            int qa = q - b*QPB;
            int a  = qa / 169;
            int r0 = (qa - a*169) * 4;
            int sel = b - b_first;
            const float* p = out + ((b*5+a)*6)*AREA + r0;
            float4 xr = *(const float4*)(p);
            float4 yr = *(const float4*)(p +   AREA);
            float4 wr = *(const float4*)(p + 2*AREA);
            float4 hr = *(const float4*)(p + 3*AREA);
            float4 cr = *(const float4*)(p + 4*AREA);

            float pas[4], cvh[4];
            __half2 hx1[2], hx2[2], hy1[2], hy2[2];
            float base = 0.f;
            {
                float xa[4] = {xr.x, xr.y, xr.z, xr.w};
                float ya[4] = {yr.x, yr.y, yr.z, yr.w};
                float wa[4] = {wr.x, wr.y, wr.z, wr.w};
                float ha[4] = {hr.x, hr.y, hr.z, hr.w};
                float ca[4] = {cr.x, cr.y, cr.z, cr.w};
                float px1[4], px2[4], py1[4], py2[4];
                #pragma unroll
                for(int u=0; u<4; u++){
                    float xv = sigmoidf(xa[u]);
                    float yv = sigmoidf(ya[u]);
                    float wv = wa[u], hv = ha[u];
                    float cv = sigmoidf(ca[u]);
                    int r = r0 + u;
                    int j = r / NHW, i = r - j*NHW;
                    float pw = __expf(wv)*c_aw[a], ph = __expf(hv)*c_ah[a];
                    float px = xv + (float)i, py = yv + (float)j;
                    px1[u] = px - 0.5f*pw; px2[u] = px + 0.5f*pw;
                    py1[u] = py - 0.5f*ph; py2[u] = py + 0.5f*ph;
                    pas[u] = 0.375f*pw*ph;
                    float dx = xv-0.5f, dy = yv-0.5f;
                    base += 0.5f*(dx*dx + dy*dy + wv*wv + hv*hv);
                    cvh[u] = 0.5f*cv*cv;
                }
                hx1[0] = __floats2half2_rn(px1[0], px1[1]); hx1[1] = __floats2half2_rn(px1[2], px1[3]);
                hx2[0] = __floats2half2_rn(px2[0], px2[1]); hx2[1] = __floats2half2_rn(px2[2], px2[3]);
                hy1[0] = __floats2half2_rn(py1[0], py1[1]); hy1[1] = __floats2half2_rn(py1[2], py1[3]);
                hy2[0] = __floats2half2_rn(py2[0], py2[1]); hy2[1] = __floats2half2_rn(py2[2], py2[3]);
            }
            const uint4*    bp = sb[sel];
            const unsigned* np = sns[sel];
            __half2 zero2 = __float2half2_rn(0.f);
            __half2 acc0 = u2h2(0xFC00FC00u), acc1 = u2h2(0xFC00FC00u);
            #pragma unroll 10
            for(int t=0; t<NBOX; t++){
                uint4 B = bp[t];
                __half2 ns  = u2h2(np[t]);
                __half2 bx1 = u2h2(B.x), bx2 = u2h2(B.y), by1 = u2h2(B.z), by2 = u2h2(B.w);
                __half2 cw0 = __hsub2(__hmin2(hx2[0], bx2), __hmax2(hx1[0], bx1));
                cw0 = __hmax2(cw0, zero2);
                __half2 ch0 = __hsub2(__hmin2(hy2[0], by2), __hmax2(hy1[0], by1));
                acc0 = __hmax2(acc0, __hfma2(cw0, ch0, ns));
                __half2 cw1 = __hsub2(__hmin2(hx2[1], bx2), __hmax2(hx1[1], bx1));
                cw1 = __hmax2(cw1, zero2);
                __half2 ch1 = __hsub2(__hmin2(hy2[1], by2), __hmax2(hy1[1], by1));
                acc1 = __hmax2(acc1, __hfma2(cw1, ch1, ns));
            }
            float a0 = __low2float(acc0), a1 = __high2float(acc0);
            float a2 = __low2float(acc1), a3 = __high2float(acc1);
            base += (a0 > pas[0]) ? 0.f : cvh[0];
            base += (a1 > pas[1]) ? 0.f : cvh[1];
            base += (a2 > pas[2]) ? 0.f : cvh[2];
            base += (a3 > pas[3]) ? 0.f : cvh[3];
            local = base;
        }
    } else if(blk < N_ENT){
        // ---- entry tables: e_cell + fp16 boxes (grid front; publishes flag) ----
        int e = blk*256 + tid;
        if(e < NENT){
            const float* g = tgt + e*5;
            float g1 = g[1];
            if(g1 == 0.0f){
                e_cell[e] = -1;
                unsigned far = duph(30000.f);
                g_bh[e]  = make_uint4(far, far, far, far);
                g_nsh[e] = duph(-1.f);
            } else {
                float gx = g1*26.f, gy = g[2]*26.f, gw = g[3]*26.f, gh = g[4]*26.f;
                g_bh[e]  = make_uint4(duph(gx-0.5f*gw), duph(gx+0.5f*gw),
                                      duph(gy-0.5f*gh), duph(gy+0.5f*gh));
                g_nsh[e] = duph(-0.375f*gw*gh);
                int bn = 0; float best = -1.f;
                #pragma unroll
                for(int a=0; a<5; a++){
                    float inter = fminf(gw, c_aw[a]) * fminf(gh, c_ah[a]);
                    float iou = inter / (gw*gh + c_aw[a]*c_ah[a] - inter);
                    if(iou > best){ best = iou; bn = a; }
                }
                int gi = (int)gx; gi = min(max(gi,0), NHW-1);
                int gj = (int)gy; gj = min(max(gj,0), NHW-1);
                int b = e / NBOX;
                e_cell[e] = b*KPOS + bn*AREA + gj*NHW + gi;
            }
        }
        __syncthreads();
        if(tid == 0){ __threadfence(); atomicAdd(&g_flag_ent, 1); }
    } else if(blk < B_MAIN0){
        // ---- per-class mean embeddings (publishes flag) ----
        int c = blk - B_ENEW0;
        __shared__ int sids[DWROWS];
        if(tid < DWROWS) sids[tid] = ids[tid];
        __syncthreads();
        int n = 0;
        #pragma unroll
        for(int r=0; r<DWROWS; r++) n += (sids[r] == c);
        if(tid == 0) g_cnt[c] = n;
        float inv = 1.f / (float)max(n, 1);
        for(int col = tid; col < DWCOLS; col += 256){
            float s = 0.f;
            #pragma unroll
            for(int r=0; r<DWROWS; r++){
                if(sids[r] == c) s += dw[r*DWCOLS + col];
            }
            g_enews[c*DWCOLS + col] = s * inv;
        }
        __syncthreads();
        if(tid == 0){ __threadfence(); atomicAdd(&g_flag_enew, 1); }
    } else if(blk >= B_CORR0 && blk < B_SAME0){
        // ---- correction for matched (winner) entries (waits for entry tables) ----
        if(tid == 0){ while(atomicAdd(&g_flag_ent, 0) < N_ENT) {} }
        __syncthreads();
        __threadfence();
        __shared__ int s_cell[256 + NBOX];
        int e0 = (blk - B_CORR0)*256;
        {
            int e1 = e0 + tid;
            s_cell[tid] = (e1 < NENT) ? e_cell[e1] : -2;
            if(tid < NBOX){
                int e2 = e0 + 256 + tid;
                s_cell[256 + tid] = (e2 < NENT) ? e_cell[e2] : -2;
            }
        }
        __syncthreads();
        int e = e0 + tid;
        if(e < NENT){
            int cell = s_cell[tid];
            if(cell >= 0){
                int b = e / NBOX, t0 = e - b*NBOX;
                bool winner = true;
                #pragma unroll 7
                for(int t2 = t0+1; t2 < NBOX; t2++)
                    winner &= (s_cell[tid + (t2 - t0)] != cell);
                if(winner){
                    const float* g = tgt + e*5;
                    float gx = g[1]*26.f, gy = g[2]*26.f, gw = g[3]*26.f, gh = g[4]*26.f;
                    int bn = 0; float best = -1.f;
                    #pragma unroll
                    for(int aa=0; aa<5; aa++){
                        float inter = fminf(gw, c_aw[aa]) * fminf(gh, c_ah[aa]);
                        float iou = inter / (gw*gh + c_aw[aa]*c_ah[aa] - inter);
                        if(iou > best){ best = iou; bn = aa; }
                    }
                    int gi = (int)gx; gi = min(max(gi,0), NHW-1);
                    int gj = (int)gy; gj = min(max(gj,0), NHW-1);
                    float tx = gx - (float)gi, ty = gy - (float)gj;
                    float twv = logf(gw / c_aw[bn]), thv = logf(gh / c_ah[bn]);

                    int k = cell - b*KPOS;
                    int a = k / AREA, r = k - a*AREA;
                    const float* p = out + ((b*5+a)*6)*AREA + r;
                    float xv = sigmoidf(p[0]);
                    float yv = sigmoidf(p[AREA]);
                    float wv = p[2*AREA];
                    float hv = p[3*AREA];
                    float cvv = sigmoidf(p[4*AREA]);
                    int j = r / NHW, i = r - j*NHW;
                    float pw = __expf(wv)*c_aw[a], ph = __expf(hv)*c_ah[a];
                    float px = xv + (float)i, py = yv + (float)j;
                    float cwg = fminf(gx+0.5f*gw, px+0.5f*pw) - fmaxf(gx-0.5f*gw, px-0.5f*pw);
                    float chg = fminf(gy+0.5f*gh, py+0.5f*ph) - fmaxf(gy-0.5f*gh, py-0.5f*ph);
                    float interg = (cwg>0.f && chg>0.f) ? cwg*chg : 0.f;
                    float tconf = interg / (gw*gh + pw*ph - interg);
                    // silent: IDENTICAL fp16 path as main (tables hold same bits)
                    float px1 = px-0.5f*pw, px2 = px+0.5f*pw;
                    float py1 = py-0.5f*ph, py2 = py+0.5f*ph;
                    float pas = 0.375f*pw*ph;
                    __half2 hx1 = __float2half2_rn(px1), hx2 = __float2half2_rn(px2);
                    __half2 hy1 = __float2half2_rn(py1), hy2 = __float2half2_rn(py2);
                    __half2 zero2 = __float2half2_rn(0.f);
                    __half2 acch = u2h2(0xFC00FC00u);
                    const uint4* bbp = g_bh + b*NBOX;
                    const unsigned* nsp = g_nsh + b*NBOX;
                    for(int t=0; t<NBOX; t++){
                        uint4 B = bbp[t];
                        __half2 cw = __hsub2(__hmin2(hx2, u2h2(B.y)), __hmax2(hx1, u2h2(B.x)));
                        cw = __hmax2(cw, zero2);
                        __half2 ch = __hsub2(__hmin2(hy2, u2h2(B.w)), __hmax2(hy1, u2h2(B.z)));
                        acch = __hmax2(acch, __hfma2(cw, ch, u2h2(nsp[t])));
                    }
                    float acc = __low2float(acch);
                    float cmd = (acc > pas) ? 0.f : 1.f;
                    float dx0 = xv-0.5f, dy0 = yv-0.5f;
                    float ldft = 0.5f*(dx0*dx0 + dy0*dy0 + wv*wv + hv*hv + cmd*cvv*cvv);
                    float dx = xv-tx, dy = yv-ty, dwv = wv-twv,
                          dh = hv-thv, dc = cvv-tconf;
                    float lmat = 0.5f*(dx*dx + dy*dy + dwv*dwv + dh*dh + 5.f*dc*dc);
                    int bsi = b / CSZ, cc = b - bsi*CSZ;
                    float v[CSZ]; float m = -3.4e38f;
                    #pragma unroll
                    for(int c2=0; c2<CSZ; c2++){
                        v[c2] = out[((bsi*CSZ+c2)*30 + a*6 + 5)*AREA + r];
                        m = fmaxf(m, v[c2]);
                    }
                    float s = 0.f;
                    #pragma unroll
                    for(int c2=0; c2<CSZ; c2++) s += __expf(v[c2]-m);
                    float lse = m + __logf(s);
                    local = lmat - ldft + (lse - v[cc]);
                }
            }
        }
    } else if(blk >= B_SAME0 && blk < B_DIFF0){
        // ---- "same" loss (waits for enews) ----
        if(tid == 0){ while(atomicAdd(&g_flag_enew, 0) < N_ENEW) {} }
        __syncthreads();
        __threadfence();
        int idx4 = (blk - B_SAME0)*256 + tid;
        int base = idx4*4;
        int r = base >> 10, c = base & 1023;
        float4 d  = *(const float4*)(dw + base);
        const float* en = g_enews + ids[r]*DWCOLS + c;
        float4 ev = *(const float4*)en;
        float a0 = d.x-ev.x, a1 = d.y-ev.y, a2 = d.z-ev.z, a3 = d.w-ev.w;
        local = a0*a0 + a1*a1 + a2*a2 + a3*a3;
    } else {
        // ---- "different" loss (waits for enews) ----
        if(tid == 0){ while(atomicAdd(&g_flag_enew, 0) < N_ENEW) {} }
        __syncthreads();
        __threadfence();
        int i = blk - B_DIFF0;
        float part[NMETA];
        #pragma unroll
        for(int j=0; j<NMETA; j++) part[j] = 0.f;
        for(int col=tid; col<DWCOLS; col+=256){
            float ei = g_enews[i*DWCOLS + col];
            #pragma unroll
            for(int j=0; j<NMETA; j++){
                float df = ei - g_enews[j*DWCOLS + col];
                part[j] += df*df;
            }
        }
        __shared__ float dmat[NMETA];
        if(tid < NMETA) dmat[tid] = 0.f;
        __syncthreads();
        int lane = tid & 31;
        #pragma unroll
        for(int j=0; j<NMETA; j++){
            float v = part[j];
            #pragma unroll
            for(int o=16; o>0; o>>=1) v += __shfl_xor_sync(0xffffffffu, v, o);
            if(lane == 0) atomicAdd(&dmat[j], v);
        }
        __syncthreads();
        if(tid == 0){
            bool pi = g_cnt[i] > 0;
            float dmin = 3.4e38f; bool any = false;
            for(int j=0; j<NMETA; j++){
                bool vp = pi && (g_cnt[j] > 0) && (j != i);
                if(vp){ any = true; dmin = fminf(dmin, dmat[j]); }
            }
            if(any) local = -dmin;
        }
    }

    // ---- block reduce (shuffle + smem atomic) + global accumulate + finalize ----
    #pragma unroll
    for(int o=16; o>0; o>>=1) local += __shfl_xor_sync(0xffffffffu, local, o);
    __shared__ float bsum;
    if(tid == 0) bsum = 0.f;
    __syncthreads();
    if((tid & 31) == 0 && local != 0.f) atomicAdd(&bsum, local);
    __syncthreads();
    if(tid == 0){
        atomicAdd(&g_acc, (double)bsum);
        __threadfence();
        int t = atomicAdd(&g_done, 1);
        if(t == NBLOCKS - 1){
            res[0] = (float)g_acc;
            g_acc       = 0.0;     // reset for next graph replay
            g_done      = 0;
            g_flag_ent  = 0;
            g_flag_enew = 0;
        }
    }
}

extern "C" void kernel_launch(void* const* d_in, const int* in_sizes, int n_in,
                              void* d_out, int out_size){
    const float* outp = (const float*)d_in[0];   // (320,30,26,26)
    const float* tgt  = (const float*)d_in[1];   // (16,20,250) == (320,50,5)
    const float* dwp  = (const float*)d_in[2];   // (1,64,1024)
    const int*   ids  = (const int*)d_in[3];     // (64,)
    float* res = (float*)d_out;

    kALL<<<NBLOCKS, 256>>>(outp, tgt, dwp, ids, res);
}

// round 9
// speedup vs baseline: 1.5409x; 1.1761x over previous
#include <cuda_runtime.h>
#include <cuda_fp16.h>

#define NB     320
#define NHW    26
#define AREA   676
#define KPOS   3380
#define NBOX   50
#define NENT   (NB*NBOX)
#define CSZ    20
#define NMETA  20
#define DWROWS 64
#define DWCOLS 1024
#define QPB    845            // quads per image
#define NQUAD  (NB*QPB)       // 270400

#define N_ENT   63
#define N_ENEW  20
#define N_CORR  63
#define N_SAME  64
#define N_DIFF  20
#define N_MAIN  1057          // ceil(NQUAD/256)
#define B_ENEW0 N_ENT                       // 63
#define B_CORR0 (B_ENEW0 + N_ENEW)          // 83
#define B_SAME0 (B_CORR0 + N_CORR)          // 146
#define B_DIFF0 (B_SAME0 + N_SAME)          // 210
#define B_MAIN0 (B_DIFF0 + N_DIFF)          // 230
#define NBLOCKS (B_MAIN0 + N_MAIN)          // 1287

__constant__ float c_aw[5] = {1.3221f, 3.19275f, 5.05587f, 9.47112f, 11.2364f};
__constant__ float c_ah[5] = {1.73145f, 4.00944f, 8.09892f, 4.84053f, 10.0071f};

__device__ double g_acc;
__device__ int    g_done;
__device__ int    g_flag_ent;
__device__ int    g_flag_enew;
__device__ int    e_cell[NENT];
__device__ uint4  g_bh[NENT];       // duplicated half2: x1,x2,y1,y2
__device__ unsigned g_nsh[NENT];    // duplicated half2 of -(0.375*gw*gh)
__device__ float  g_enews[NMETA*DWCOLS];
__device__ int    g_cnt[NMETA];

__device__ __forceinline__ float sigmoidf(float v){ return 1.f/(1.f+__expf(-v)); }
__device__ __forceinline__ unsigned duph(float v){
    return (unsigned)__half_as_ushort(__float2half_rn(v)) * 0x10001u;
}
union H2U { unsigned u; __half2 h; };
__device__ __forceinline__ __half2 u2h2(unsigned v){ H2U c; c.u = v; return c.h; }

__global__ void __launch_bounds__(256, 5) kALL(const float* __restrict__ out,
                                               const float* __restrict__ tgt,
                                               const float* __restrict__ dw,
                                               const int*   __restrict__ ids,
                                               float* __restrict__ res){
    int blk = blockIdx.x, tid = threadIdx.x;
    float local = 0.f;

    if(blk >= B_MAIN0){
        // ---- default per-cell loss over global quad index, fp16x2 silence ----
        int mb = blk - B_MAIN0;
        int q  = mb*256 + tid;
        bool valid = q < NQUAD;
        int qc = valid ? q : NQUAD - 1;
        int b  = qc / QPB;
        int qa = qc - b*QPB;
        int a  = qa / 169;
        int r0 = (qa - a*169) * 4;

        // issue global loads EARLY (before smem build + barrier)
        const float* p = out + ((b*5+a)*6)*AREA + r0;
        float4 xr = *(const float4*)(p);
        float4 yr = *(const float4*)(p +   AREA);
        float4 wr = *(const float4*)(p + 2*AREA);
        float4 hr = *(const float4*)(p + 3*AREA);
        float4 cr = *(const float4*)(p + 4*AREA);

        __shared__ uint4    sb[2][NBOX];
        __shared__ unsigned sns[2][NBOX];
        int b_first = (mb*256) / QPB;
        {   // build fp16 box tables for the <=2 images this block spans
            int w = -1, bb2 = 0;
            if(tid < NBOX){ w = 0; bb2 = b_first; }
            else if(tid >= 64 && tid < 64 + NBOX){ w = 1; bb2 = min(b_first + 1, NB - 1); }
            if(w >= 0){
                int t = (w == 0) ? tid : tid - 64;
                const float* g = tgt + (bb2*NBOX + t)*5;
                float g1 = g[1];
                if(g1 == 0.0f){
                    unsigned far = duph(30000.f);
                    sb[w][t]  = make_uint4(far, far, far, far);
                    sns[w][t] = duph(-1.f);
                } else {
                    float gx = g1*26.f, gy = g[2]*26.f, gw = g[3]*26.f, gh = g[4]*26.f;
                    sb[w][t]  = make_uint4(duph(gx-0.5f*gw), duph(gx+0.5f*gw),
                                           duph(gy-0.5f*gh), duph(gy+0.5f*gh));
                    sns[w][t] = duph(-0.375f*gw*gh);
                }
            }
        }
        __syncthreads();

        int sel = b - b_first;
        float pas[4], cvh[4];
        __half2 hx1[2], hx2[2], hy1[2], hy2[2];
        float base = 0.f;
        {
            float xa[4] = {xr.x, xr.y, xr.z, xr.w};
            float ya[4] = {yr.x, yr.y, yr.z, yr.w};
            float wa[4] = {wr.x, wr.y, wr.z, wr.w};
            float ha[4] = {hr.x, hr.y, hr.z, hr.w};
            float ca[4] = {cr.x, cr.y, cr.z, cr.w};
            float px1[4], px2[4], py1[4], py2[4];
            #pragma unroll
            for(int u=0; u<4; u++){
                float xv = sigmoidf(xa[u]);
                float yv = sigmoidf(ya[u]);
                float wv = wa[u], hv = ha[u];
                float cv = sigmoidf(ca[u]);
                int r = r0 + u;
                int j = r / NHW, i = r - j*NHW;
                float pw = __expf(wv)*c_aw[a], ph = __expf(hv)*c_ah[a];
                float px = xv + (float)i, py = yv + (float)j;
                px1[u] = px - 0.5f*pw; px2[u] = px + 0.5f*pw;
                py1[u] = py - 0.5f*ph; py2[u] = py + 0.5f*ph;
                pas[u] = 0.375f*pw*ph;
                float dx = xv-0.5f, dy = yv-0.5f;
                base += 0.5f*(dx*dx + dy*dy + wv*wv + hv*hv);
                cvh[u] = 0.5f*cv*cv;
            }
            hx1[0] = __floats2half2_rn(px1[0], px1[1]); hx1[1] = __floats2half2_rn(px1[2], px1[3]);
            hx2[0] = __floats2half2_rn(px2[0], px2[1]); hx2[1] = __floats2half2_rn(px2[2], px2[3]);
            hy1[0] = __floats2half2_rn(py1[0], py1[1]); hy1[1] = __floats2half2_rn(py1[2], py1[3]);
            hy2[0] = __floats2half2_rn(py2[0], py2[1]); hy2[1] = __floats2half2_rn(py2[2], py2[3]);
        }
        const uint4*    bp = sb[sel];
        const unsigned* np = sns[sel];
        __half2 zero2 = __float2half2_rn(0.f);
        __half2 acc0 = u2h2(0xFC00FC00u), acc1 = u2h2(0xFC00FC00u);
        #pragma unroll
        for(int t=0; t<NBOX; t++){
            uint4 B = bp[t];
            __half2 ns  = u2h2(np[t]);
            __half2 bx1 = u2h2(B.x), bx2 = u2h2(B.y), by1 = u2h2(B.z), by2 = u2h2(B.w);
            __half2 cw0 = __hsub2(__hmin2(hx2[0], bx2), __hmax2(hx1[0], bx1));
            cw0 = __hmax2(cw0, zero2);
            __half2 ch0 = __hsub2(__hmin2(hy2[0], by2), __hmax2(hy1[0], by1));
            acc0 = __hmax2(acc0, __hfma2(cw0, ch0, ns));
            __half2 cw1 = __hsub2(__hmin2(hx2[1], bx2), __hmax2(hx1[1], bx1));
            cw1 = __hmax2(cw1, zero2);
            __half2 ch1 = __hsub2(__hmin2(hy2[1], by2), __hmax2(hy1[1], by1));
            acc1 = __hmax2(acc1, __hfma2(cw1, ch1, ns));
        }
        float a0 = __low2float(acc0), a1 = __high2float(acc0);
        float a2 = __low2float(acc1), a3 = __high2float(acc1);
        base += (a0 > pas[0]) ? 0.f : cvh[0];
        base += (a1 > pas[1]) ? 0.f : cvh[1];
        base += (a2 > pas[2]) ? 0.f : cvh[2];
        base += (a3 > pas[3]) ? 0.f : cvh[3];
        local = valid ? base : 0.f;
    } else if(blk < N_ENT){
        // ---- entry tables: e_cell + fp16 boxes (publishes flag) ----
        int e = blk*256 + tid;
        if(e < NENT){
            const float* g = tgt + e*5;
            float g1 = g[1];
            if(g1 == 0.0f){
                e_cell[e] = -1;
                unsigned far = duph(30000.f);
                g_bh[e]  = make_uint4(far, far, far, far);
                g_nsh[e] = duph(-1.f);
            } else {
                float gx = g1*26.f, gy = g[2]*26.f, gw = g[3]*26.f, gh = g[4]*26.f;
                g_bh[e]  = make_uint4(duph(gx-0.5f*gw), duph(gx+0.5f*gw),
                                      duph(gy-0.5f*gh), duph(gy+0.5f*gh));
                g_nsh[e] = duph(-0.375f*gw*gh);
                int bn = 0; float best = -1.f;
                #pragma unroll
                for(int a=0; a<5; a++){
                    float inter = fminf(gw, c_aw[a]) * fminf(gh, c_ah[a]);
                    float iou = inter / (gw*gh + c_aw[a]*c_ah[a] - inter);
                    if(iou > best){ best = iou; bn = a; }
                }
                int gi = (int)gx; gi = min(max(gi,0), NHW-1);
                int gj = (int)gy; gj = min(max(gj,0), NHW-1);
                int b = e / NBOX;
                e_cell[e] = b*KPOS + bn*AREA + gj*NHW + gi;
            }
        }
        __syncthreads();
        if(tid == 0){ __threadfence(); atomicAdd(&g_flag_ent, 1); }
    } else if(blk < B_CORR0){
        // ---- per-class mean embeddings (publishes flag) ----
        int c = blk - B_ENEW0;
        __shared__ int sids[DWROWS];
        if(tid < DWROWS) sids[tid] = ids[tid];
        __syncthreads();
        int n = 0;
        #pragma unroll
        for(int r=0; r<DWROWS; r++) n += (sids[r] == c);
        if(tid == 0) g_cnt[c] = n;
        float inv = 1.f / (float)max(n, 1);
        for(int col = tid; col < DWCOLS; col += 256){
            float s = 0.f;
            #pragma unroll
            for(int r=0; r<DWROWS; r++){
                if(sids[r] == c) s += dw[r*DWCOLS + col];
            }
            g_enews[c*DWCOLS + col] = s * inv;
        }
        __syncthreads();
        if(tid == 0){ __threadfence(); atomicAdd(&g_flag_enew, 1); }
    } else if(blk < B_SAME0){
        // ---- correction for matched (winner) entries (waits for entry tables) ----
        if(tid == 0){ while(atomicAdd(&g_flag_ent, 0) < N_ENT) {} }
        __syncthreads();
        __threadfence();
        __shared__ int s_cell[256 + NBOX];
        int e0 = (blk - B_CORR0)*256;
        {
            int e1 = e0 + tid;
            s_cell[tid] = (e1 < NENT) ? e_cell[e1] : -2;
            if(tid < NBOX){
                int e2 = e0 + 256 + tid;
                s_cell[256 + tid] = (e2 < NENT) ? e_cell[e2] : -2;
            }
        }
        __syncthreads();
        int e = e0 + tid;
        if(e < NENT){
            int cell = s_cell[tid];
            if(cell >= 0){
                int b = e / NBOX, t0 = e - b*NBOX;
                bool winner = true;
                #pragma unroll 7
                for(int t2 = t0+1; t2 < NBOX; t2++)
                    winner &= (s_cell[tid + (t2 - t0)] != cell);
                if(winner){
                    const float* g = tgt + e*5;
                    float gx = g[1]*26.f, gy = g[2]*26.f, gw = g[3]*26.f, gh = g[4]*26.f;
                    int bn = 0; float best = -1.f;
                    #pragma unroll
                    for(int aa=0; aa<5; aa++){
                        float inter = fminf(gw, c_aw[aa]) * fminf(gh, c_ah[aa]);
                        float iou = inter / (gw*gh + c_aw[aa]*c_ah[aa] - inter);
                        if(iou > best){ best = iou; bn = aa; }
                    }
                    int gi = (int)gx; gi = min(max(gi,0), NHW-1);
                    int gj = (int)gy; gj = min(max(gj,0), NHW-1);
                    float tx = gx - (float)gi, ty = gy - (float)gj;
                    float twv = logf(gw / c_aw[bn]), thv = logf(gh / c_ah[bn]);

                    int k = cell - b*KPOS;
                    int a = k / AREA, r = k - a*AREA;
                    const float* p = out + ((b*5+a)*6)*AREA + r;
                    float xv = sigmoidf(p[0]);
                    float yv = sigmoidf(p[AREA]);
                    float wv = p[2*AREA];
                    float hv = p[3*AREA];
                    float cvv = sigmoidf(p[4*AREA]);
                    int j = r / NHW, i = r - j*NHW;
                    float pw = __expf(wv)*c_aw[a], ph = __expf(hv)*c_ah[a];
                    float px = xv + (float)i, py = yv + (float)j;
                    float cwg = fminf(gx+0.5f*gw, px+0.5f*pw) - fmaxf(gx-0.5f*gw, px-0.5f*pw);
                    float chg = fminf(gy+0.5f*gh, py+0.5f*ph) - fmaxf(gy-0.5f*gh, py-0.5f*ph);
                    float interg = (cwg>0.f && chg>0.f) ? cwg*chg : 0.f;
                    float tconf = interg / (gw*gh + pw*ph - interg);
                    // silent: IDENTICAL fp16 path as main (tables hold same bits)
                    float px1 = px-0.5f*pw, px2 = px+0.5f*pw;
                    float py1 = py-0.5f*ph, py2 = py+0.5f*ph;
                    float pas = 0.375f*pw*ph;
                    __half2 hx1 = __float2half2_rn(px1), hx2 = __float2half2_rn(px2);
                    __half2 hy1 = __float2half2_rn(py1), hy2 = __float2half2_rn(py2);
                    __half2 zero2 = __float2half2_rn(0.f);
                    __half2 acch = u2h2(0xFC00FC00u);
                    const uint4* bbp = g_bh + b*NBOX;
                    const unsigned* nsp = g_nsh + b*NBOX;
                    for(int t=0; t<NBOX; t++){
                        uint4 B = bbp[t];
                        __half2 cw = __hsub2(__hmin2(hx2, u2h2(B.y)), __hmax2(hx1, u2h2(B.x)));
                        cw = __hmax2(cw, zero2);
                        __half2 ch = __hsub2(__hmin2(hy2, u2h2(B.w)), __hmax2(hy1, u2h2(B.z)));
                        acch = __hmax2(acch, __hfma2(cw, ch, u2h2(nsp[t])));
                    }
                    float acc = __low2float(acch);
                    float cmd = (acc > pas) ? 0.f : 1.f;
                    float dx0 = xv-0.5f, dy0 = yv-0.5f;
                    float ldft = 0.5f*(dx0*dx0 + dy0*dy0 + wv*wv + hv*hv + cmd*cvv*cvv);
                    float dx = xv-tx, dy = yv-ty, dwv = wv-twv,
                          dh = hv-thv, dc = cvv-tconf;
                    float lmat = 0.5f*(dx*dx + dy*dy + dwv*dwv + dh*dh + 5.f*dc*dc);
                    int bsi = b / CSZ, cc = b - bsi*CSZ;
                    float v[CSZ]; float m = -3.4e38f;
                    #pragma unroll
                    for(int c2=0; c2<CSZ; c2++){
                        v[c2] = out[((bsi*CSZ+c2)*30 + a*6 + 5)*AREA + r];
                        m = fmaxf(m, v[c2]);
                    }
                    float s = 0.f;
                    #pragma unroll
                    for(int c2=0; c2<CSZ; c2++) s += __expf(v[c2]-m);
                    float lse = m + __logf(s);
                    local = lmat - ldft + (lse - v[cc]);
                }
            }
        }
    } else if(blk < B_DIFF0){
        // ---- "same" loss (waits for enews) ----
        if(tid == 0){ while(atomicAdd(&g_flag_enew, 0) < N_ENEW) {} }
        __syncthreads();
        __threadfence();
        int idx4 = (blk - B_SAME0)*256 + tid;
        int base = idx4*4;
        int r = base >> 10, c = base & 1023;
        float4 d  = *(const float4*)(dw + base);
        const float* en = g_enews + ids[r]*DWCOLS + c;
        float4 ev = *(const float4*)en;
        float a0 = d.x-ev.x, a1 = d.y-ev.y, a2 = d.z-ev.z, a3 = d.w-ev.w;
        local = a0*a0 + a1*a1 + a2*a2 + a3*a3;
    } else {
        // ---- "different" loss (waits for enews) ----
        if(tid == 0){ while(atomicAdd(&g_flag_enew, 0) < N_ENEW) {} }
        __syncthreads();
        __threadfence();
        int i = blk - B_DIFF0;
        float part[NMETA];
        #pragma unroll
        for(int j=0; j<NMETA; j++) part[j] = 0.f;
        for(int col=tid; col<DWCOLS; col+=256){
            float ei = g_enews[i*DWCOLS + col];
            #pragma unroll
            for(int j=0; j<NMETA; j++){
                float df = ei - g_enews[j*DWCOLS + col];
                part[j] += df*df;
            }
        }
        __shared__ float dmat[NMETA];
        if(tid < NMETA) dmat[tid] = 0.f;
        __syncthreads();
        int lane = tid & 31;
        #pragma unroll
        for(int j=0; j<NMETA; j++){
            float v = part[j];
            #pragma unroll
            for(int o=16; o>0; o>>=1) v += __shfl_xor_sync(0xffffffffu, v, o);
            if(lane == 0) atomicAdd(&dmat[j], v);
        }
        __syncthreads();
        if(tid == 0){
            bool pi = g_cnt[i] > 0;
            float dmin = 3.4e38f; bool any = false;
            for(int j=0; j<NMETA; j++){
                bool vp = pi && (g_cnt[j] > 0) && (j != i);
                if(vp){ any = true; dmin = fminf(dmin, dmat[j]); }
            }
            if(any) local = -dmin;
        }
    }

    // ---- block reduce (shuffle + smem atomic) + global accumulate + finalize ----
    #pragma unroll
    for(int o=16; o>0; o>>=1) local += __shfl_xor_sync(0xffffffffu, local, o);
    __shared__ float bsum;
    if(tid == 0) bsum = 0.f;
    __syncthreads();
    if((tid & 31) == 0 && local != 0.f) atomicAdd(&bsum, local);
    __syncthreads();
    if(tid == 0){
        atomicAdd(&g_acc, (double)bsum);
        __threadfence();
        int t = atomicAdd(&g_done, 1);
        if(t == NBLOCKS - 1){
            res[0] = (float)g_acc;
            g_acc       = 0.0;     // reset for next graph replay
            g_done      = 0;
            g_flag_ent  = 0;
            g_flag_enew = 0;
        }
    }
}

extern "C" void kernel_launch(void* const* d_in, const int* in_sizes, int n_in,
                              void* d_out, int out_size){
    const float* outp = (const float*)d_in[0];   // (320,30,26,26)
    const float* tgt  = (const float*)d_in[1];   // (16,20,250) == (320,50,5)
    const float* dwp  = (const float*)d_in[2];   // (1,64,1024)
    const int*   ids  = (const int*)d_in[3];     // (64,)
    float* res = (float*)d_out;

    kALL<<<NBLOCKS, 256>>>(outp, tgt, dwp, ids, res);
}